// round 16
// baseline (speedup 1.0000x reference)
#include <cuda_runtime.h>
#include <math.h>

#define NBLK 608          // 4 CTAs/SM x 152 SMs, single wave, 32 warps/SM (measured optimum)
#define NTHR 256
#define NCOL 256

#define FX_SCALE 1073741824.0   // 2^30 fixed-point scale

// 256 column accumulators, Q34.30 fixed point, plus a completion counter.
// Zero at module load; the last block resets them each call so graph replays
// stay deterministic.
__device__ unsigned long long g_acc[NCOL];
__device__ unsigned int g_count;

// Blackwell 256-bit global load: 8 consecutive floats in one LDG.256.
__device__ __forceinline__ void ldg256(const float* a, float4& lo, float4& hi) {
    asm volatile("ld.global.v8.f32 {%0,%1,%2,%3,%4,%5,%6,%7}, [%8];"
                 : "=f"(lo.x), "=f"(lo.y), "=f"(lo.z), "=f"(lo.w),
                   "=f"(hi.x), "=f"(hi.y), "=f"(hi.z), "=f"(hi.w)
                 : "l"(a));
}

__global__ void __launch_bounds__(NTHR, 4)
colsq_fused_kernel(const float* __restrict__ d, long long n_f8,
                   float* __restrict__ out) {
    const int tid = threadIdx.x;

    // Each thread owns a fixed 8-column group: base float index =
    // (block*256+tid)*8, and the stride (608*256*8 floats) is a multiple
    // of 256, so columns (tid*8)&255 .. +7 are invariant per thread.
    long long idx = (long long)blockIdx.x * NTHR + tid;      // in float8 units
    const long long stride = (long long)gridDim.x * NTHR;    // in float8 units

    float a0 = 0.f, a1 = 0.f, a2 = 0.f, a3 = 0.f;
    float a4 = 0.f, a5 = 0.f, a6 = 0.f, a7 = 0.f;

    // Unroll x4: 4 independent LDG.256 in flight (128B/thread, same as 8x128-bit).
    long long i = idx;
    for (; i + 3 * stride < n_f8; i += 4 * stride) {
        float4 l0, h0, l1, h1, l2, h2, l3, h3;
        ldg256(d + (i            ) * 8, l0, h0);
        ldg256(d + (i +     stride) * 8, l1, h1);
        ldg256(d + (i + 2 * stride) * 8, l2, h2);
        ldg256(d + (i + 3 * stride) * 8, l3, h3);
        a0 += l0.x * l0.x; a1 += l0.y * l0.y; a2 += l0.z * l0.z; a3 += l0.w * l0.w;
        a4 += h0.x * h0.x; a5 += h0.y * h0.y; a6 += h0.z * h0.z; a7 += h0.w * h0.w;
        a0 += l1.x * l1.x; a1 += l1.y * l1.y; a2 += l1.z * l1.z; a3 += l1.w * l1.w;
        a4 += h1.x * h1.x; a5 += h1.y * h1.y; a6 += h1.z * h1.z; a7 += h1.w * h1.w;
        a0 += l2.x * l2.x; a1 += l2.y * l2.y; a2 += l2.z * l2.z; a3 += l2.w * l2.w;
        a4 += h2.x * h2.x; a5 += h2.y * h2.y; a6 += h2.z * h2.z; a7 += h2.w * h2.w;
        a0 += l3.x * l3.x; a1 += l3.y * l3.y; a2 += l3.z * l3.z; a3 += l3.w * l3.w;
        a4 += h3.x * h3.x; a5 += h3.y * h3.y; a6 += h3.z * h3.z; a7 += h3.w * h3.w;
    }
    for (; i < n_f8; i += stride) {
        float4 l, h;
        ldg256(d + i * 8, l, h);
        a0 += l.x * l.x; a1 += l.y * l.y; a2 += l.z * l.z; a3 += l.w * l.w;
        a4 += h.x * h.x; a5 += h.y * h.y; a6 += h.z * h.z; a7 += h.w * h.w;
    }

    // Deterministic block reduction: 8 replicas of the 256-column vector.
    // Thread tid owns columns c..c+7 where c = (tid*8) & 255; replica = tid>>5.
    __shared__ float s[8][NCOL];
    const int c = (tid * 8) & (NCOL - 1);
    const int rep = tid >> 5;  // 0..7
    s[rep][c + 0] = a0;
    s[rep][c + 1] = a1;
    s[rep][c + 2] = a2;
    s[rep][c + 3] = a3;
    s[rep][c + 4] = a4;
    s[rep][c + 5] = a5;
    s[rep][c + 6] = a6;
    s[rep][c + 7] = a7;
    __syncthreads();

    // One thread per column: fold 8 replicas, convert to Q34.30 fixed point,
    // relaxed integer RED into the L2-resident column accumulator.
    // Integer addition is associative -> bit-deterministic result.
    float part = ((s[0][tid] + s[1][tid]) + (s[2][tid] + s[3][tid]))
               + ((s[4][tid] + s[5][tid]) + (s[6][tid] + s[7][tid]));
    long long fx = llrintf(part * (float)FX_SCALE);
    atomicAdd(&g_acc[tid], (unsigned long long)fx);

    // --- last-block-done, fence-free (no CCTL.IVALL) ---
    __shared__ bool isLast;
    __syncthreads();
    if (tid == 0) {
        unsigned int old;
        asm volatile("atom.add.release.gpu.u32 %0, [%1], %2;"
                     : "=r"(old) : "l"(&g_count), "r"(1u) : "memory");
        isLast = (old == (unsigned)(NBLK - 1));
    }
    __syncthreads();
    if (!isLast) return;

    if (tid == 0) {
        unsigned int tmp;
        asm volatile("ld.acquire.gpu.u32 %0, [%1];"
                     : "=r"(tmp) : "l"(&g_count) : "memory");
    }
    __syncthreads();

    // Epilogue: 2 KB from L2, reduce 256 -> 1, write scalar, reset state.
    unsigned long long raw = __ldcg(&g_acc[tid]);
    g_acc[tid] = 0ull;                         // reset for next graph replay

    double colsum = (double)(long long)raw * (1.0 / FX_SCALE);
    double diff = colsum - 1.0;

    __shared__ double red[NCOL];
    red[tid] = diff * diff;
    __syncthreads();

    #pragma unroll
    for (int off = NCOL / 2; off >= 32; off >>= 1) {
        if (tid < off) red[tid] += red[tid + off];
        __syncthreads();
    }
    if (tid < 32) {
        double v = red[tid];
        #pragma unroll
        for (int off = 16; off > 0; off >>= 1)
            v += __shfl_down_sync(0xFFFFFFFF, v, off);
        if (tid == 0) {
            out[0] = (float)(0.001 * sqrt(v));
            g_count = 0;                       // reset counter for next replay
        }
    }
}

extern "C" void kernel_launch(void* const* d_in, const int* in_sizes, int n_in,
                              void* d_out, int out_size) {
    const float* d = (const float*)d_in[0];
    float* out = (float*)d_out;
    long long n = (long long)in_sizes[0];      // 262144 * 256
    long long n_f8 = n / 8;

    colsq_fused_kernel<<<NBLK, NTHR>>>(d, n_f8, out);
}